// round 4
// baseline (speedup 1.0000x reference)
#include <cuda_runtime.h>
#include <cuda_bf16.h>

#define N_NODES 100000
#define N_EDGES 1600000
#define IN_F 128
#define H_F 64
#define OUT_F 32

// ---------------- scratch (device globals: no allocation allowed) ----------
__device__ int   d_deg [N_NODES];
__device__ float d_dinv[N_NODES];
__device__ float d_g1  [N_NODES * H_F];    // dinv-scaled layer-1 transform
__device__ float d_s1  [N_NODES * H_F];    // aggregation accumulator L1
__device__ float d_g2  [N_NODES * OUT_F];  // dinv-scaled layer-2 transform
__device__ float d_s2  [N_NODES * OUT_F];  // aggregation accumulator L2

// ---------------- degree: deg[i] = indeg(i) + 1 (self loop) ----------------
__global__ void init_deg_kernel() {
    int i = blockIdx.x * blockDim.x + threadIdx.x;
    if (i < N_NODES) d_deg[i] = 1;
}

__global__ void count_deg_kernel(const int* __restrict__ ei) {
    int e = blockIdx.x * blockDim.x + threadIdx.x;
    if (e < N_EDGES) atomicAdd(&d_deg[ei[N_EDGES + e]], 1);
}

__global__ void dinv_kernel() {
    int i = blockIdx.x * blockDim.x + threadIdx.x;
    if (i < N_NODES) d_dinv[i] = rsqrtf((float)d_deg[i]);
}

// ---------------- GEMM1: g1[i,c] = dinv[i] * (x[i,:] . W1[c,:]) ------------
// Also seeds s1 = g1 (self-loop contribution).
// Block: 256 threads, 64 rows/block in 4 groups of 16; thread computes
// 4 rows x 1 col.  W1 staged transposed in smem with pitch 65 (no conflicts).
__global__ void gemm1_kernel(const float* __restrict__ x,
                             const float* __restrict__ W1) {
    __shared__ float W1t[128 * 65];
    __shared__ float xs[16 * 128];
    const int tid = threadIdx.x;

    for (int idx = tid; idx < H_F * IN_F; idx += 256) {
        int c = idx >> 7;          // 0..63
        int k = idx & 127;         // 0..127
        W1t[k * 65 + c] = W1[idx]; // coalesced read, conflict-free write
    }
    __syncthreads();

    const int row0 = blockIdx.x * 64;
    const int r0   = (tid >> 6) * 4;   // 0,4,8,12
    const int col  = tid & 63;

    for (int g = 0; g < 4; ++g) {
        const int rbase = row0 + g * 16;
        __syncthreads();
        for (int idx = tid; idx < 16 * 128; idx += 256) {
            int rl = idx >> 7, k = idx & 127;
            int row = rbase + rl;
            xs[idx] = (row < N_NODES) ? x[row * IN_F + k] : 0.f;
        }
        __syncthreads();

        float acc[4] = {0.f, 0.f, 0.f, 0.f};
        #pragma unroll 8
        for (int k = 0; k < 128; ++k) {
            float w = W1t[k * 65 + col];
            #pragma unroll
            for (int i = 0; i < 4; ++i)
                acc[i] += xs[(r0 + i) * 128 + k] * w;
        }
        #pragma unroll
        for (int i = 0; i < 4; ++i) {
            int row = rbase + r0 + i;
            if (row < N_NODES) {
                float v = acc[i] * d_dinv[row];
                d_g1[row * H_F + col] = v;
                d_s1[row * H_F + col] = v;
            }
        }
    }
}

// ---------------- scatter L1: s1[dst] += g1[src], float4-vectorized --------
__global__ void scatter1_kernel(const int* __restrict__ ei) {
    int t = blockIdx.x * blockDim.x + threadIdx.x;   // E*16 items
    int e = t >> 4;
    int q = t & 15;
    int s = __ldg(&ei[e]);
    int d = __ldg(&ei[N_EDGES + e]);
    float4 v = *reinterpret_cast<const float4*>(&d_g1[s * H_F + q * 4]);
    float* dp = &d_s1[d * H_F + q * 4];
    atomicAdd(dp + 0, v.x);
    atomicAdd(dp + 1, v.y);
    atomicAdd(dp + 2, v.z);
    atomicAdd(dp + 3, v.w);
}

// ---------------- GEMM2: fused relu(dinv*s1 + b1) @ W2^T, dinv-scaled ------
// g2[i,k] = dinv[i] * sum_j W2[k,j] * relu(dinv[i]*s1[i,j] + b1[j]); s2 = g2.
__global__ void gemm2_kernel(const float* __restrict__ W2,
                             const float* __restrict__ b1) {
    __shared__ float W2t[64 * 33];
    __shared__ float b1s[64];
    __shared__ float hbuf[16 * 64];
    const int tid = threadIdx.x;

    for (int idx = tid; idx < OUT_F * H_F; idx += 256) {
        int c = idx >> 6;          // 0..31
        int j = idx & 63;          // 0..63
        W2t[j * 33 + c] = W2[idx];
    }
    if (tid < 64) b1s[tid] = b1[tid];
    __syncthreads();

    const int row0 = blockIdx.x * 64;
    const int r0   = (tid >> 5) * 2;   // 0,2,...,14
    const int col  = tid & 31;

    for (int g = 0; g < 4; ++g) {
        const int rbase = row0 + g * 16;
        __syncthreads();
        for (int idx = tid; idx < 16 * 64; idx += 256) {
            int rl = idx >> 6, j = idx & 63;
            int row = rbase + rl;
            float h = 0.f;
            if (row < N_NODES) {
                float di = d_dinv[row];
                h = fmaxf(di * d_s1[row * H_F + j] + b1s[j], 0.f);
            }
            hbuf[idx] = h;
        }
        __syncthreads();

        float acc[2] = {0.f, 0.f};
        #pragma unroll 8
        for (int j = 0; j < 64; ++j) {
            float w = W2t[j * 33 + col];
            acc[0] += hbuf[(r0 + 0) * 64 + j] * w;
            acc[1] += hbuf[(r0 + 1) * 64 + j] * w;
        }
        #pragma unroll
        for (int i = 0; i < 2; ++i) {
            int row = rbase + r0 + i;
            if (row < N_NODES) {
                float v = acc[i] * d_dinv[row];
                d_g2[row * OUT_F + col] = v;
                d_s2[row * OUT_F + col] = v;
            }
        }
    }
}

// ---------------- scatter L2: s2[dst] += g2[src] ---------------------------
__global__ void scatter2_kernel(const int* __restrict__ ei) {
    int t = blockIdx.x * blockDim.x + threadIdx.x;   // E*8 items
    int e = t >> 3;
    int q = t & 7;
    int s = __ldg(&ei[e]);
    int d = __ldg(&ei[N_EDGES + e]);
    float4 v = *reinterpret_cast<const float4*>(&d_g2[s * OUT_F + q * 4]);
    float* dp = &d_s2[d * OUT_F + q * 4];
    atomicAdd(dp + 0, v.x);
    atomicAdd(dp + 1, v.y);
    atomicAdd(dp + 2, v.z);
    atomicAdd(dp + 3, v.w);
}

// ---------------- final: out[i,k] = dinv[i]*s2[i,k] + b2[k] ----------------
__global__ void final_kernel(const float* __restrict__ b2,
                             float* __restrict__ out) {
    int t = blockIdx.x * blockDim.x + threadIdx.x;   // N*32 items
    if (t < N_NODES * OUT_F) {
        int node = t >> 5;
        int k = t & 31;
        out[t] = d_dinv[node] * d_s2[t] + b2[k];
    }
}

extern "C" void kernel_launch(void* const* d_in, const int* in_sizes, int n_in,
                              void* d_out, int out_size) {
    const float* x  = (const float*)d_in[0];
    const int*   ei = (const int*)  d_in[1];
    const float* W1 = (const float*)d_in[2];
    const float* b1 = (const float*)d_in[3];
    const float* W2 = (const float*)d_in[4];
    const float* b2 = (const float*)d_in[5];
    float* out = (float*)d_out;

    init_deg_kernel <<<(N_NODES + 255) / 256, 256>>>();
    count_deg_kernel<<<(N_EDGES + 255) / 256, 256>>>(ei);
    dinv_kernel     <<<(N_NODES + 255) / 256, 256>>>();

    gemm1_kernel    <<<(N_NODES + 63) / 64, 256>>>(x, W1);
    scatter1_kernel <<<(N_EDGES * 16) / 256, 256>>>(ei);   // exact multiple

    gemm2_kernel    <<<(N_NODES + 63) / 64, 256>>>(W2, b1);
    scatter2_kernel <<<(N_EDGES * 8) / 256, 256>>>(ei);    // exact multiple

    final_kernel    <<<(N_NODES * OUT_F + 255) / 256, 256>>>(b2, out);
}

// round 5
// speedup vs baseline: 2.3370x; 2.3370x over previous
#include <cuda_runtime.h>
#include <cuda_bf16.h>

#define N_NODES 100000
#define N_EDGES 1600000
#define IN_F 128
#define H_F 64
#define OUT_F 32
#define SCAN_BLK 1024
#define NB_SCAN ((N_NODES + SCAN_BLK - 1) / SCAN_BLK)   // 98

// ---------------- scratch (device globals: no allocation allowed) ----------
__device__ int   d_cnt      [N_NODES];          // in-degree (edges only)
__device__ float d_dinv     [N_NODES];
__device__ int   d_rowptr   [N_NODES + 1];
__device__ int   d_cursor   [N_NODES];
__device__ int   d_bsum     [128];
__device__ int   d_srcsorted[N_EDGES];          // CSR-by-dst src list
__device__ float d_g1       [N_NODES * H_F];    // dinv-scaled layer-1 transform
__device__ float d_h1       [N_NODES * H_F];    // relu(dinv*agg + b1)
__device__ float d_g2       [N_NODES * OUT_F];  // dinv-scaled layer-2 transform

// ---------------- degree counting ------------------------------------------
__global__ void zero_cnt_kernel() {
    int i = blockIdx.x * blockDim.x + threadIdx.x;
    if (i < N_NODES) d_cnt[i] = 0;
}

__global__ void count_kernel(const int* __restrict__ ei) {
    int e = blockIdx.x * blockDim.x + threadIdx.x;
    if (e < N_EDGES) atomicAdd(&d_cnt[ei[N_EDGES + e]], 1);
}

__global__ void dinv_kernel() {
    int i = blockIdx.x * blockDim.x + threadIdx.x;
    if (i < N_NODES) d_dinv[i] = rsqrtf((float)(d_cnt[i] + 1));  // +1 self loop
}

// ---------------- exclusive scan of d_cnt -> d_rowptr -----------------------
__global__ void scan_a_kernel() {
    __shared__ int sh[SCAN_BLK];
    int tid = threadIdx.x;
    int gid = blockIdx.x * SCAN_BLK + tid;
    int v = (gid < N_NODES) ? d_cnt[gid] : 0;
    sh[tid] = v;
    __syncthreads();
    for (int off = 1; off < SCAN_BLK; off <<= 1) {
        int t = (tid >= off) ? sh[tid - off] : 0;
        __syncthreads();
        sh[tid] += t;
        __syncthreads();
    }
    if (gid < N_NODES) d_rowptr[gid] = sh[tid] - v;   // block-local exclusive
    if (tid == SCAN_BLK - 1) d_bsum[blockIdx.x] = sh[tid];
}

__global__ void scan_b_kernel() {
    __shared__ int sh[128];
    int tid = threadIdx.x;
    int v = (tid < NB_SCAN) ? d_bsum[tid] : 0;
    sh[tid] = v;
    __syncthreads();
    for (int off = 1; off < 128; off <<= 1) {
        int t = (tid >= off) ? sh[tid - off] : 0;
        __syncthreads();
        sh[tid] += t;
        __syncthreads();
    }
    if (tid < NB_SCAN) d_bsum[tid] = sh[tid] - v;     // exclusive
}

__global__ void scan_c_kernel() {
    int gid = blockIdx.x * blockDim.x + threadIdx.x;
    if (gid < N_NODES) {
        int r = d_rowptr[gid] + d_bsum[gid >> 10];
        d_rowptr[gid] = r;
        d_cursor[gid] = r;
    }
    if (gid == 0) d_rowptr[N_NODES] = N_EDGES;
}

// ---------------- CSR fill: src_sorted grouped by dst -----------------------
__global__ void fill_kernel(const int* __restrict__ ei) {
    int e = blockIdx.x * blockDim.x + threadIdx.x;
    if (e < N_EDGES) {
        int s = ei[e];
        int d = ei[N_EDGES + e];
        int pos = atomicAdd(&d_cursor[d], 1);
        d_srcsorted[pos] = s;
    }
}

// ---------------- GEMM1: g1[i,c] = dinv[i] * (x[i,:] . W1[c,:]) -------------
// Block: 256 threads, tile 64 rows x 64 cols, thread 4x4.
// xs transposed [k][row] pitch 68 (LDS.128 over 4 rows), W chunk transposed
// [k][col] pitch 68 (LDS.128 over 4 cols) -> 2 LDS / 16 FMA per k.
__global__ void gemm1_kernel(const float* __restrict__ x,
                             const float* __restrict__ W1) {
    __shared__ float xs[128 * 68];   // 34816 B
    __shared__ float Wt[32 * 68];    //  8704 B
    const int tid = threadIdx.x;
    const int row0 = blockIdx.x * 64;

    // xs_t[k][r] = x[row0+r][k]  (coalesced read, 4-way-conflict write)
    for (int idx = tid; idx < 64 * 128; idx += 256) {
        int r = idx >> 7, k = idx & 127;
        int row = row0 + r;
        xs[k * 68 + r] = (row < N_NODES) ? x[row * IN_F + k] : 0.f;
    }

    const int r0 = (tid >> 4) * 4;   // 0..60
    const int c0 = (tid & 15) * 4;   // 0..60
    float acc[4][4] = {};

    for (int kc = 0; kc < 4; ++kc) {
        __syncthreads();
        // Wt[kl][c] = W1[c][kc*32+kl]  (coalesced read)
        for (int idx = tid; idx < 64 * 32; idx += 256) {
            int c = idx >> 5, kl = idx & 31;
            Wt[kl * 68 + c] = W1[c * IN_F + kc * 32 + kl];
        }
        __syncthreads();
        #pragma unroll
        for (int kl = 0; kl < 32; ++kl) {
            int k = kc * 32 + kl;
            float4 xv = *reinterpret_cast<const float4*>(&xs[k * 68 + r0]);
            float4 wv = *reinterpret_cast<const float4*>(&Wt[kl * 68 + c0]);
            acc[0][0] += xv.x * wv.x; acc[0][1] += xv.x * wv.y;
            acc[0][2] += xv.x * wv.z; acc[0][3] += xv.x * wv.w;
            acc[1][0] += xv.y * wv.x; acc[1][1] += xv.y * wv.y;
            acc[1][2] += xv.y * wv.z; acc[1][3] += xv.y * wv.w;
            acc[2][0] += xv.z * wv.x; acc[2][1] += xv.z * wv.y;
            acc[2][2] += xv.z * wv.z; acc[2][3] += xv.z * wv.w;
            acc[3][0] += xv.w * wv.x; acc[3][1] += xv.w * wv.y;
            acc[3][2] += xv.w * wv.z; acc[3][3] += xv.w * wv.w;
        }
    }

    #pragma unroll
    for (int i = 0; i < 4; ++i) {
        int row = row0 + r0 + i;
        if (row < N_NODES) {
            float di = d_dinv[row];
            float4 o = make_float4(acc[i][0] * di, acc[i][1] * di,
                                   acc[i][2] * di, acc[i][3] * di);
            *reinterpret_cast<float4*>(&d_g1[row * H_F + c0]) = o;
        }
    }
}

// ---------------- gather L1 (CSR) + relu + bias ------------------------------
// One warp per dst node; lane handles 2 features (float2, 256B/edge coalesced).
__global__ void gather1_kernel(const float* __restrict__ b1) {
    int warp = (blockIdx.x * blockDim.x + threadIdx.x) >> 5;
    int lane = threadIdx.x & 31;
    if (warp >= N_NODES) return;

    const float2* g = reinterpret_cast<const float2*>(d_g1);
    float2 acc = g[warp * 32 + lane];               // self loop
    int e = d_rowptr[warp];
    const int end = d_rowptr[warp + 1];

    for (; e + 4 <= end; e += 4) {
        int s0 = __ldg(&d_srcsorted[e + 0]);
        int s1 = __ldg(&d_srcsorted[e + 1]);
        int s2 = __ldg(&d_srcsorted[e + 2]);
        int s3 = __ldg(&d_srcsorted[e + 3]);
        float2 v0 = __ldg(&g[s0 * 32 + lane]);
        float2 v1 = __ldg(&g[s1 * 32 + lane]);
        float2 v2 = __ldg(&g[s2 * 32 + lane]);
        float2 v3 = __ldg(&g[s3 * 32 + lane]);
        acc.x += (v0.x + v1.x) + (v2.x + v3.x);
        acc.y += (v0.y + v1.y) + (v2.y + v3.y);
    }
    for (; e < end; ++e) {
        int s = __ldg(&d_srcsorted[e]);
        float2 v = __ldg(&g[s * 32 + lane]);
        acc.x += v.x; acc.y += v.y;
    }

    float di = d_dinv[warp];
    float2 b = __ldg(reinterpret_cast<const float2*>(b1) + lane);
    float2 h;
    h.x = fmaxf(fmaf(di, acc.x, b.x), 0.f);
    h.y = fmaxf(fmaf(di, acc.y, b.y), 0.f);
    reinterpret_cast<float2*>(d_h1)[warp * 32 + lane] = h;
}

// ---------------- GEMM2: g2[i,c] = dinv[i] * (h1[i,:] . W2[c,:]) -------------
// Block: 256 threads, tile 64 rows x 32 cols, thread 2x4.
__global__ void gemm2_kernel(const float* __restrict__ W2) {
    __shared__ float ht[64 * 66];    // ht[j][r], 16896 B
    __shared__ float Wt[64 * 36];    // Wt[j][c],  9216 B
    const int tid = threadIdx.x;
    const int row0 = blockIdx.x * 64;

    for (int idx = tid; idx < 64 * 64; idx += 256) {
        int r = idx >> 6, j = idx & 63;
        int row = row0 + r;
        ht[j * 66 + r] = (row < N_NODES) ? d_h1[row * H_F + j] : 0.f;
    }
    for (int idx = tid; idx < 32 * 64; idx += 256) {
        int c = idx >> 6, j = idx & 63;
        Wt[j * 36 + c] = W2[c * H_F + j];
    }
    __syncthreads();

    const int r0 = (tid >> 3) * 2;   // 0..62
    const int c0 = (tid & 7) * 4;    // 0..28
    float acc[2][4] = {};

    #pragma unroll
    for (int j = 0; j < 64; ++j) {
        float2 hv = *reinterpret_cast<const float2*>(&ht[j * 66 + r0]);
        float4 wv = *reinterpret_cast<const float4*>(&Wt[j * 36 + c0]);
        acc[0][0] += hv.x * wv.x; acc[0][1] += hv.x * wv.y;
        acc[0][2] += hv.x * wv.z; acc[0][3] += hv.x * wv.w;
        acc[1][0] += hv.y * wv.x; acc[1][1] += hv.y * wv.y;
        acc[1][2] += hv.y * wv.z; acc[1][3] += hv.y * wv.w;
    }

    #pragma unroll
    for (int i = 0; i < 2; ++i) {
        int row = row0 + r0 + i;
        if (row < N_NODES) {
            float di = d_dinv[row];
            float4 o = make_float4(acc[i][0] * di, acc[i][1] * di,
                                   acc[i][2] * di, acc[i][3] * di);
            *reinterpret_cast<float4*>(&d_g2[row * OUT_F + c0]) = o;
        }
    }
}

// ---------------- gather L2 (CSR) + bias -> output ---------------------------
// One warp per dst node; lane handles 1 feature (128B/edge coalesced).
__global__ void gather2_kernel(const float* __restrict__ b2,
                               float* __restrict__ out) {
    int warp = (blockIdx.x * blockDim.x + threadIdx.x) >> 5;
    int lane = threadIdx.x & 31;
    if (warp >= N_NODES) return;

    float acc = d_g2[warp * OUT_F + lane];          // self loop
    int e = d_rowptr[warp];
    const int end = d_rowptr[warp + 1];

    for (; e + 4 <= end; e += 4) {
        int s0 = __ldg(&d_srcsorted[e + 0]);
        int s1 = __ldg(&d_srcsorted[e + 1]);
        int s2 = __ldg(&d_srcsorted[e + 2]);
        int s3 = __ldg(&d_srcsorted[e + 3]);
        float v0 = __ldg(&d_g2[s0 * OUT_F + lane]);
        float v1 = __ldg(&d_g2[s1 * OUT_F + lane]);
        float v2 = __ldg(&d_g2[s2 * OUT_F + lane]);
        float v3 = __ldg(&d_g2[s3 * OUT_F + lane]);
        acc += (v0 + v1) + (v2 + v3);
    }
    for (; e < end; ++e) {
        int s = __ldg(&d_srcsorted[e]);
        acc += __ldg(&d_g2[s * OUT_F + lane]);
    }

    out[warp * OUT_F + lane] = fmaf(d_dinv[warp], acc, __ldg(&b2[lane]));
}

extern "C" void kernel_launch(void* const* d_in, const int* in_sizes, int n_in,
                              void* d_out, int out_size) {
    const float* x  = (const float*)d_in[0];
    const int*   ei = (const int*)  d_in[1];
    const float* W1 = (const float*)d_in[2];
    const float* b1 = (const float*)d_in[3];
    const float* W2 = (const float*)d_in[4];
    const float* b2 = (const float*)d_in[5];
    float* out = (float*)d_out;

    zero_cnt_kernel<<<(N_NODES + 255) / 256, 256>>>();
    count_kernel   <<<(N_EDGES + 255) / 256, 256>>>(ei);
    dinv_kernel    <<<(N_NODES + 255) / 256, 256>>>();

    scan_a_kernel  <<<NB_SCAN, SCAN_BLK>>>();
    scan_b_kernel  <<<1, 128>>>();
    scan_c_kernel  <<<(N_NODES + 255) / 256, 256>>>();
    fill_kernel    <<<(N_EDGES + 255) / 256, 256>>>(ei);

    gemm1_kernel   <<<(N_NODES + 63) / 64, 256>>>(x, W1);
    gather1_kernel <<<(N_NODES * 32 + 255) / 256, 256>>>(b1);

    gemm2_kernel   <<<(N_NODES + 63) / 64, 256>>>(W2);
    gather2_kernel <<<(N_NODES * 32 + 255) / 256, 256>>>(b2, out);
}

// round 7
// speedup vs baseline: 2.4230x; 1.0368x over previous
#include <cuda_runtime.h>
#include <cuda_fp16.h>

#define N_NODES 100000
#define N_EDGES 1600000
#define IN_F 128
#define H_F 64
#define OUT_F 32
#define SCAN_BLK 1024
#define NB_SCAN ((N_NODES + SCAN_BLK - 1) / SCAN_BLK)   // 98

// ---------------- scratch (device globals: no allocation allowed) ----------
__device__ int    d_cnt      [N_NODES + 32];       // padded for int4 zeroing
__device__ float  d_dinv     [N_NODES];
__device__ int    d_rowptr   [N_NODES + 1];
__device__ int    d_cursor   [N_NODES];
__device__ int    d_bsum     [128];
__device__ int    d_srcsorted[N_EDGES];            // CSR-by-dst src list
__device__ __half d_g1       [N_NODES * H_F];      // dinv-scaled L1 transform (fp16)
__device__ float  d_h1       [N_NODES * H_F];      // relu(dinv*agg + b1)
__device__ __half d_g2       [N_NODES * OUT_F];    // dinv-scaled L2 transform (fp16)

// ---------------- zero counters (int4) --------------------------------------
__global__ void zero_cnt_kernel() {
    int i = blockIdx.x * blockDim.x + threadIdx.x;
    if (i < (N_NODES + 3) / 4)
        reinterpret_cast<int4*>(d_cnt)[i] = make_int4(0, 0, 0, 0);
}

// ---------------- degree counting (2 edges / thread; 800000/256 = 3125) -----
__global__ void count_kernel(const int* __restrict__ ei) {
    int t = blockIdx.x * blockDim.x + threadIdx.x;   // E/2 threads exactly
    int2 d = reinterpret_cast<const int2*>(ei + N_EDGES)[t];
    atomicAdd(&d_cnt[d.x], 1);
    atomicAdd(&d_cnt[d.y], 1);
}

// ---------------- exclusive scan of d_cnt -> d_rowptr (warp shuffles) -------
__global__ void scan_a_kernel() {
    __shared__ int wpre[32];
    const int tid  = threadIdx.x;
    const int lane = tid & 31;
    const int wid  = tid >> 5;
    const int gid  = blockIdx.x * SCAN_BLK + tid;
    int v = (gid < N_NODES) ? d_cnt[gid] : 0;

    int inc = v;
    #pragma unroll
    for (int o = 1; o < 32; o <<= 1) {
        int t = __shfl_up_sync(0xffffffffu, inc, o);
        if (lane >= o) inc += t;
    }
    if (lane == 31) wpre[wid] = inc;
    __syncthreads();
    if (wid == 0) {
        int s = wpre[lane];
        #pragma unroll
        for (int o = 1; o < 32; o <<= 1) {
            int t = __shfl_up_sync(0xffffffffu, s, o);
            if (lane >= o) s += t;
        }
        wpre[lane] = s;                      // inclusive warp-sum scan
    }
    __syncthreads();
    int base = (wid > 0) ? wpre[wid - 1] : 0;
    if (gid < N_NODES) d_rowptr[gid] = base + inc - v;   // block-local exclusive
    if (tid == SCAN_BLK - 1) d_bsum[blockIdx.x] = wpre[31];
}

__global__ void scan_b_kernel() {
    __shared__ int sh[128];
    int tid = threadIdx.x;
    int v = (tid < NB_SCAN) ? d_bsum[tid] : 0;
    sh[tid] = v;
    __syncthreads();
    for (int off = 1; off < 128; off <<= 1) {
        int t = (tid >= off) ? sh[tid - off] : 0;
        __syncthreads();
        sh[tid] += t;
        __syncthreads();
    }
    if (tid < NB_SCAN) d_bsum[tid] = sh[tid] - v;        // exclusive
}

// scan_c: globalize rowptr, seed cursor, AND compute dinv (fused)
__global__ void scan_c_kernel() {
    int gid = blockIdx.x * blockDim.x + threadIdx.x;
    if (gid < N_NODES) {
        int r = d_rowptr[gid] + d_bsum[gid >> 10];
        d_rowptr[gid] = r;
        d_cursor[gid] = r;
        d_dinv[gid] = rsqrtf((float)(d_cnt[gid] + 1));   // +1 self loop
    }
    if (gid == 0) d_rowptr[N_NODES] = N_EDGES;
}

// ---------------- CSR fill (2 edges / thread; exact grid) -------------------
__global__ void fill_kernel(const int* __restrict__ ei) {
    int t = blockIdx.x * blockDim.x + threadIdx.x;   // E/2 threads exactly
    int2 s = reinterpret_cast<const int2*>(ei)[t];
    int2 d = reinterpret_cast<const int2*>(ei + N_EDGES)[t];
    d_srcsorted[atomicAdd(&d_cursor[d.x], 1)] = s.x;
    d_srcsorted[atomicAdd(&d_cursor[d.y], 1)] = s.y;
}

// ---------------- GEMM1: g1[i,c] = fp16( dinv[i] * (x[i,:] . W1[c,:]) ) -----
// 256 threads, tile 64x64, thread 4x4; both operands transposed in smem.
__global__ void gemm1_kernel(const float* __restrict__ x,
                             const float* __restrict__ W1) {
    __shared__ float xs[128 * 68];
    __shared__ float Wt[32 * 68];
    const int tid = threadIdx.x;
    const int row0 = blockIdx.x * 64;

    for (int idx = tid; idx < 64 * 128; idx += 256) {
        int r = idx >> 7, k = idx & 127;
        int row = row0 + r;
        xs[k * 68 + r] = (row < N_NODES) ? x[row * IN_F + k] : 0.f;
    }

    const int r0 = (tid >> 4) * 4;
    const int c0 = (tid & 15) * 4;
    float acc[4][4] = {};

    for (int kc = 0; kc < 4; ++kc) {
        __syncthreads();
        for (int idx = tid; idx < 64 * 32; idx += 256) {
            int c = idx >> 5, kl = idx & 31;
            Wt[kl * 68 + c] = W1[c * IN_F + kc * 32 + kl];
        }
        __syncthreads();
        #pragma unroll
        for (int kl = 0; kl < 32; ++kl) {
            int k = kc * 32 + kl;
            float4 xv = *reinterpret_cast<const float4*>(&xs[k * 68 + r0]);
            float4 wv = *reinterpret_cast<const float4*>(&Wt[kl * 68 + c0]);
            acc[0][0] += xv.x * wv.x; acc[0][1] += xv.x * wv.y;
            acc[0][2] += xv.x * wv.z; acc[0][3] += xv.x * wv.w;
            acc[1][0] += xv.y * wv.x; acc[1][1] += xv.y * wv.y;
            acc[1][2] += xv.y * wv.z; acc[1][3] += xv.y * wv.w;
            acc[2][0] += xv.z * wv.x; acc[2][1] += xv.z * wv.y;
            acc[2][2] += xv.z * wv.z; acc[2][3] += xv.z * wv.w;
            acc[3][0] += xv.w * wv.x; acc[3][1] += xv.w * wv.y;
            acc[3][2] += xv.w * wv.z; acc[3][3] += xv.w * wv.w;
        }
    }

    #pragma unroll
    for (int i = 0; i < 4; ++i) {
        int row = row0 + r0 + i;
        if (row < N_NODES) {
            float di = d_dinv[row];
            __half2 p0 = __floats2half2_rn(acc[i][0] * di, acc[i][1] * di);
            __half2 p1 = __floats2half2_rn(acc[i][2] * di, acc[i][3] * di);
            __half2* dst = reinterpret_cast<__half2*>(&d_g1[row * H_F + c0]);
            dst[0] = p0;
            dst[1] = p1;
        }
    }
}

// ---------------- gather L1 (CSR, fp16) + relu + bias ------------------------
// One warp per dst node; lane handles 2 features (half2, 128B/edge coalesced).
__global__ void gather1_kernel(const float* __restrict__ b1) {
    int warp = (blockIdx.x * blockDim.x + threadIdx.x) >> 5;
    int lane = threadIdx.x & 31;
    if (warp >= N_NODES) return;

    const __half2* g = reinterpret_cast<const __half2*>(d_g1);
    float2 acc = __half22float2(g[warp * 32 + lane]);    // self loop
    int e = d_rowptr[warp];
    const int end = d_rowptr[warp + 1];

    for (; e + 4 <= end; e += 4) {
        int s0 = __ldg(&d_srcsorted[e + 0]);
        int s1 = __ldg(&d_srcsorted[e + 1]);
        int s2 = __ldg(&d_srcsorted[e + 2]);
        int s3 = __ldg(&d_srcsorted[e + 3]);
        float2 v0 = __half22float2(__ldg(&g[s0 * 32 + lane]));
        float2 v1 = __half22float2(__ldg(&g[s1 * 32 + lane]));
        float2 v2 = __half22float2(__ldg(&g[s2 * 32 + lane]));
        float2 v3 = __half22float2(__ldg(&g[s3 * 32 + lane]));
        acc.x += (v0.x + v1.x) + (v2.x + v3.x);
        acc.y += (v0.y + v1.y) + (v2.y + v3.y);
    }
    for (; e < end; ++e) {
        int s = __ldg(&d_srcsorted[e]);
        float2 v = __half22float2(__ldg(&g[s * 32 + lane]));
        acc.x += v.x; acc.y += v.y;
    }

    float di = d_dinv[warp];
    float2 b = __ldg(reinterpret_cast<const float2*>(b1) + lane);
    float2 h;
    h.x = fmaxf(fmaf(di, acc.x, b.x), 0.f);
    h.y = fmaxf(fmaf(di, acc.y, b.y), 0.f);
    reinterpret_cast<float2*>(d_h1)[warp * 32 + lane] = h;
}

// ---------------- GEMM2: g2[i,c] = fp16( dinv[i] * (h1[i,:] . W2[c,:]) ) -----
__global__ void gemm2_kernel(const float* __restrict__ W2) {
    __shared__ float ht[64 * 66];
    __shared__ float Wt[64 * 36];
    const int tid = threadIdx.x;
    const int row0 = blockIdx.x * 64;

    for (int idx = tid; idx < 64 * 64; idx += 256) {
        int r = idx >> 6, j = idx & 63;
        int row = row0 + r;
        ht[j * 66 + r] = (row < N_NODES) ? d_h1[row * H_F + j] : 0.f;
    }
    for (int idx = tid; idx < 32 * 64; idx += 256) {
        int c = idx >> 6, j = idx & 63;
        Wt[j * 36 + c] = W2[c * H_F + j];
    }
    __syncthreads();

    const int r0 = (tid >> 3) * 2;
    const int c0 = (tid & 7) * 4;
    float acc[2][4] = {};

    #pragma unroll
    for (int j = 0; j < 64; ++j) {
        float2 hv = *reinterpret_cast<const float2*>(&ht[j * 66 + r0]);
        float4 wv = *reinterpret_cast<const float4*>(&Wt[j * 36 + c0]);
        acc[0][0] += hv.x * wv.x; acc[0][1] += hv.x * wv.y;
        acc[0][2] += hv.x * wv.z; acc[0][3] += hv.x * wv.w;
        acc[1][0] += hv.y * wv.x; acc[1][1] += hv.y * wv.y;
        acc[1][2] += hv.y * wv.z; acc[1][3] += hv.y * wv.w;
    }

    #pragma unroll
    for (int i = 0; i < 2; ++i) {
        int row = row0 + r0 + i;
        if (row < N_NODES) {
            float di = d_dinv[row];
            __half2 p0 = __floats2half2_rn(acc[i][0] * di, acc[i][1] * di);
            __half2 p1 = __floats2half2_rn(acc[i][2] * di, acc[i][3] * di);
            __half2* dst = reinterpret_cast<__half2*>(&d_g2[row * OUT_F + c0]);
            dst[0] = p0;
            dst[1] = p1;
        }
    }
}

// ---------------- gather L2 (CSR, fp16) + bias -> output ---------------------
// One warp per dst node; lane handles 1 feature (64B/edge coalesced).
__global__ void gather2_kernel(const float* __restrict__ b2,
                               float* __restrict__ out) {
    int warp = (blockIdx.x * blockDim.x + threadIdx.x) >> 5;
    int lane = threadIdx.x & 31;
    if (warp >= N_NODES) return;

    float acc = __half2float(d_g2[warp * OUT_F + lane]);   // self loop
    int e = d_rowptr[warp];
    const int end = d_rowptr[warp + 1];

    for (; e + 4 <= end; e += 4) {
        int s0 = __ldg(&d_srcsorted[e + 0]);
        int s1 = __ldg(&d_srcsorted[e + 1]);
        int s2 = __ldg(&d_srcsorted[e + 2]);
        int s3 = __ldg(&d_srcsorted[e + 3]);
        float v0 = __half2float(__ldg(&d_g2[s0 * OUT_F + lane]));
        float v1 = __half2float(__ldg(&d_g2[s1 * OUT_F + lane]));
        float v2 = __half2float(__ldg(&d_g2[s2 * OUT_F + lane]));
        float v3 = __half2float(__ldg(&d_g2[s3 * OUT_F + lane]));
        acc += (v0 + v1) + (v2 + v3);
    }
    for (; e < end; ++e) {
        int s = __ldg(&d_srcsorted[e]);
        acc += __half2float(__ldg(&d_g2[s * OUT_F + lane]));
    }

    out[warp * OUT_F + lane] = fmaf(d_dinv[warp], acc, __ldg(&b2[lane]));
}

extern "C" void kernel_launch(void* const* d_in, const int* in_sizes, int n_in,
                              void* d_out, int out_size) {
    const float* x  = (const float*)d_in[0];
    const int*   ei = (const int*)  d_in[1];
    const float* W1 = (const float*)d_in[2];
    const float* b1 = (const float*)d_in[3];
    const float* W2 = (const float*)d_in[4];
    const float* b2 = (const float*)d_in[5];
    float* out = (float*)d_out;

    zero_cnt_kernel<<<(N_NODES / 4 + 256) / 256, 256>>>();
    count_kernel   <<<(N_EDGES / 2) / 256, 256>>>(ei);   // 3125 blocks, exact
    scan_a_kernel  <<<NB_SCAN, SCAN_BLK>>>();
    scan_b_kernel  <<<1, 128>>>();
    scan_c_kernel  <<<(N_NODES + 255) / 256, 256>>>();
    fill_kernel    <<<(N_EDGES / 2) / 256, 256>>>(ei);   // 3125 blocks, exact

    gemm1_kernel   <<<(N_NODES + 63) / 64, 256>>>(x, W1);
    gather1_kernel <<<(N_NODES * 32 + 255) / 256, 256>>>(b1);

    gemm2_kernel   <<<(N_NODES + 63) / 64, 256>>>(W2);
    gather2_kernel <<<(N_NODES * 32 + 255) / 256, 256>>>(b2, out);
}

// round 8
// speedup vs baseline: 2.4238x; 1.0003x over previous
#include <cuda_runtime.h>
#include <cuda_fp16.h>

#define N_NODES 100000
#define N_EDGES 1600000
#define IN_F 128
#define H_F 64
#define OUT_F 32
#define SCAN_BLK 1024
#define NB_SCAN ((N_NODES + SCAN_BLK - 1) / SCAN_BLK)   // 98

// ---------------- scratch (device globals: no allocation allowed) ----------
__device__ int    d_cnt      [N_NODES + 32];       // padded for int4 zeroing
__device__ float  d_dinv     [N_NODES];
__device__ int    d_rowptr   [N_NODES + 1];
__device__ int    d_cursor   [N_NODES];
__device__ int    d_bsum     [128];
__device__ int    d_srcsorted[N_EDGES];            // CSR-by-dst src list
__device__ __half d_g1       [N_NODES * H_F];      // dinv-scaled L1 transform (fp16)
__device__ float  d_h1       [N_NODES * H_F];      // relu(dinv*agg + b1)
__device__ __half d_g2       [N_NODES * OUT_F];    // dinv-scaled L2 transform (fp16)

// ---------------- zero counters (int4) --------------------------------------
__global__ void zero_cnt_kernel() {
    int i = blockIdx.x * blockDim.x + threadIdx.x;
    if (i < (N_NODES + 3) / 4)
        reinterpret_cast<int4*>(d_cnt)[i] = make_int4(0, 0, 0, 0);
}

// ---------------- degree counting (2 edges / thread; 800000/256 = 3125) -----
__global__ void count_kernel(const int* __restrict__ ei) {
    int t = blockIdx.x * blockDim.x + threadIdx.x;   // E/2 threads exactly
    int2 d = reinterpret_cast<const int2*>(ei + N_EDGES)[t];
    atomicAdd(&d_cnt[d.x], 1);
    atomicAdd(&d_cnt[d.y], 1);
}

// ---------------- exclusive scan of d_cnt -> d_rowptr (warp shuffles) -------
__global__ void scan_a_kernel() {
    __shared__ int wpre[32];
    const int tid  = threadIdx.x;
    const int lane = tid & 31;
    const int wid  = tid >> 5;
    const int gid  = blockIdx.x * SCAN_BLK + tid;
    int v = (gid < N_NODES) ? d_cnt[gid] : 0;

    int inc = v;
    #pragma unroll
    for (int o = 1; o < 32; o <<= 1) {
        int t = __shfl_up_sync(0xffffffffu, inc, o);
        if (lane >= o) inc += t;
    }
    if (lane == 31) wpre[wid] = inc;
    __syncthreads();
    if (wid == 0) {
        int s = wpre[lane];
        #pragma unroll
        for (int o = 1; o < 32; o <<= 1) {
            int t = __shfl_up_sync(0xffffffffu, s, o);
            if (lane >= o) s += t;
        }
        wpre[lane] = s;                      // inclusive warp-sum scan
    }
    __syncthreads();
    int base = (wid > 0) ? wpre[wid - 1] : 0;
    if (gid < N_NODES) d_rowptr[gid] = base + inc - v;   // block-local exclusive
    if (tid == SCAN_BLK - 1) d_bsum[blockIdx.x] = wpre[31];
}

__global__ void scan_b_kernel() {
    __shared__ int sh[128];
    int tid = threadIdx.x;
    int v = (tid < NB_SCAN) ? d_bsum[tid] : 0;
    sh[tid] = v;
    __syncthreads();
    for (int off = 1; off < 128; off <<= 1) {
        int t = (tid >= off) ? sh[tid - off] : 0;
        __syncthreads();
        sh[tid] += t;
        __syncthreads();
    }
    if (tid < NB_SCAN) d_bsum[tid] = sh[tid] - v;        // exclusive
}

// scan_c: globalize rowptr, seed cursor, AND compute dinv (fused)
__global__ void scan_c_kernel() {
    int gid = blockIdx.x * blockDim.x + threadIdx.x;
    if (gid < N_NODES) {
        int r = d_rowptr[gid] + d_bsum[gid >> 10];
        d_rowptr[gid] = r;
        d_cursor[gid] = r;
        d_dinv[gid] = rsqrtf((float)(d_cnt[gid] + 1));   // +1 self loop
    }
    if (gid == 0) d_rowptr[N_NODES] = N_EDGES;
}

// ---------------- CSR fill (2 edges / thread; exact grid) -------------------
__global__ void fill_kernel(const int* __restrict__ ei) {
    int t = blockIdx.x * blockDim.x + threadIdx.x;   // E/2 threads exactly
    int2 s = reinterpret_cast<const int2*>(ei)[t];
    int2 d = reinterpret_cast<const int2*>(ei + N_EDGES)[t];
    d_srcsorted[atomicAdd(&d_cursor[d.x], 1)] = s.x;
    d_srcsorted[atomicAdd(&d_cursor[d.y], 1)] = s.y;
}

// ---------------- GEMM1: g1[i,c] = fp16( dinv[i] * (x[i,:] . W1[c,:]) ) -----
// 256 threads, tile 64x64, thread 4x4; both operands transposed in smem.
__global__ void gemm1_kernel(const float* __restrict__ x,
                             const float* __restrict__ W1) {
    __shared__ float xs[128 * 68];
    __shared__ float Wt[32 * 68];
    const int tid = threadIdx.x;
    const int row0 = blockIdx.x * 64;

    for (int idx = tid; idx < 64 * 128; idx += 256) {
        int r = idx >> 7, k = idx & 127;
        int row = row0 + r;
        xs[k * 68 + r] = (row < N_NODES) ? x[row * IN_F + k] : 0.f;
    }

    const int r0 = (tid >> 4) * 4;
    const int c0 = (tid & 15) * 4;
    float acc[4][4] = {};

    for (int kc = 0; kc < 4; ++kc) {
        __syncthreads();
        for (int idx = tid; idx < 64 * 32; idx += 256) {
            int c = idx >> 5, kl = idx & 31;
            Wt[kl * 68 + c] = W1[c * IN_F + kc * 32 + kl];
        }
        __syncthreads();
        #pragma unroll
        for (int kl = 0; kl < 32; ++kl) {
            int k = kc * 32 + kl;
            float4 xv = *reinterpret_cast<const float4*>(&xs[k * 68 + r0]);
            float4 wv = *reinterpret_cast<const float4*>(&Wt[kl * 68 + c0]);
            acc[0][0] += xv.x * wv.x; acc[0][1] += xv.x * wv.y;
            acc[0][2] += xv.x * wv.z; acc[0][3] += xv.x * wv.w;
            acc[1][0] += xv.y * wv.x; acc[1][1] += xv.y * wv.y;
            acc[1][2] += xv.y * wv.z; acc[1][3] += xv.y * wv.w;
            acc[2][0] += xv.z * wv.x; acc[2][1] += xv.z * wv.y;
            acc[2][2] += xv.z * wv.z; acc[2][3] += xv.z * wv.w;
            acc[3][0] += xv.w * wv.x; acc[3][1] += xv.w * wv.y;
            acc[3][2] += xv.w * wv.z; acc[3][3] += xv.w * wv.w;
        }
    }

    #pragma unroll
    for (int i = 0; i < 4; ++i) {
        int row = row0 + r0 + i;
        if (row < N_NODES) {
            float di = d_dinv[row];
            __half2 p0 = __floats2half2_rn(acc[i][0] * di, acc[i][1] * di);
            __half2 p1 = __floats2half2_rn(acc[i][2] * di, acc[i][3] * di);
            __half2* dst = reinterpret_cast<__half2*>(&d_g1[row * H_F + c0]);
            dst[0] = p0;
            dst[1] = p1;
        }
    }
}

// ---------------- gather L1 (CSR, fp16) + relu + bias ------------------------
// One warp per dst node; lane handles 2 features (half2, 128B/edge coalesced).
__global__ void gather1_kernel(const float* __restrict__ b1) {
    int warp = (blockIdx.x * blockDim.x + threadIdx.x) >> 5;
    int lane = threadIdx.x & 31;
    if (warp >= N_NODES) return;

    const __half2* g = reinterpret_cast<const __half2*>(d_g1);
    float2 acc = __half22float2(g[warp * 32 + lane]);    // self loop
    int e = d_rowptr[warp];
    const int end = d_rowptr[warp + 1];

    for (; e + 4 <= end; e += 4) {
        int s0 = __ldg(&d_srcsorted[e + 0]);
        int s1 = __ldg(&d_srcsorted[e + 1]);
        int s2 = __ldg(&d_srcsorted[e + 2]);
        int s3 = __ldg(&d_srcsorted[e + 3]);
        float2 v0 = __half22float2(__ldg(&g[s0 * 32 + lane]));
        float2 v1 = __half22float2(__ldg(&g[s1 * 32 + lane]));
        float2 v2 = __half22float2(__ldg(&g[s2 * 32 + lane]));
        float2 v3 = __half22float2(__ldg(&g[s3 * 32 + lane]));
        acc.x += (v0.x + v1.x) + (v2.x + v3.x);
        acc.y += (v0.y + v1.y) + (v2.y + v3.y);
    }
    for (; e < end; ++e) {
        int s = __ldg(&d_srcsorted[e]);
        float2 v = __half22float2(__ldg(&g[s * 32 + lane]));
        acc.x += v.x; acc.y += v.y;
    }

    float di = d_dinv[warp];
    float2 b = __ldg(reinterpret_cast<const float2*>(b1) + lane);
    float2 h;
    h.x = fmaxf(fmaf(di, acc.x, b.x), 0.f);
    h.y = fmaxf(fmaf(di, acc.y, b.y), 0.f);
    reinterpret_cast<float2*>(d_h1)[warp * 32 + lane] = h;
}

// ---------------- GEMM2: g2[i,c] = fp16( dinv[i] * (h1[i,:] . W2[c,:]) ) -----
__global__ void gemm2_kernel(const float* __restrict__ W2) {
    __shared__ float ht[64 * 66];
    __shared__ float Wt[64 * 36];
    const int tid = threadIdx.x;
    const int row0 = blockIdx.x * 64;

    for (int idx = tid; idx < 64 * 64; idx += 256) {
        int r = idx >> 6, j = idx & 63;
        int row = row0 + r;
        ht[j * 66 + r] = (row < N_NODES) ? d_h1[row * H_F + j] : 0.f;
    }
    for (int idx = tid; idx < 32 * 64; idx += 256) {
        int c = idx >> 6, j = idx & 63;
        Wt[j * 36 + c] = W2[c * H_F + j];
    }
    __syncthreads();

    const int r0 = (tid >> 3) * 2;
    const int c0 = (tid & 7) * 4;
    float acc[2][4] = {};

    #pragma unroll
    for (int j = 0; j < 64; ++j) {
        float2 hv = *reinterpret_cast<const float2*>(&ht[j * 66 + r0]);
        float4 wv = *reinterpret_cast<const float4*>(&Wt[j * 36 + c0]);
        acc[0][0] += hv.x * wv.x; acc[0][1] += hv.x * wv.y;
        acc[0][2] += hv.x * wv.z; acc[0][3] += hv.x * wv.w;
        acc[1][0] += hv.y * wv.x; acc[1][1] += hv.y * wv.y;
        acc[1][2] += hv.y * wv.z; acc[1][3] += hv.y * wv.w;
    }

    #pragma unroll
    for (int i = 0; i < 2; ++i) {
        int row = row0 + r0 + i;
        if (row < N_NODES) {
            float di = d_dinv[row];
            __half2 p0 = __floats2half2_rn(acc[i][0] * di, acc[i][1] * di);
            __half2 p1 = __floats2half2_rn(acc[i][2] * di, acc[i][3] * di);
            __half2* dst = reinterpret_cast<__half2*>(&d_g2[row * OUT_F + c0]);
            dst[0] = p0;
            dst[1] = p1;
        }
    }
}

// ---------------- gather L2 (CSR, fp16) + bias -> output ---------------------
// One warp per dst node; lane handles 1 feature (64B/edge coalesced).
__global__ void gather2_kernel(const float* __restrict__ b2,
                               float* __restrict__ out) {
    int warp = (blockIdx.x * blockDim.x + threadIdx.x) >> 5;
    int lane = threadIdx.x & 31;
    if (warp >= N_NODES) return;

    float acc = __half2float(d_g2[warp * OUT_F + lane]);   // self loop
    int e = d_rowptr[warp];
    const int end = d_rowptr[warp + 1];

    for (; e + 4 <= end; e += 4) {
        int s0 = __ldg(&d_srcsorted[e + 0]);
        int s1 = __ldg(&d_srcsorted[e + 1]);
        int s2 = __ldg(&d_srcsorted[e + 2]);
        int s3 = __ldg(&d_srcsorted[e + 3]);
        float v0 = __half2float(__ldg(&d_g2[s0 * OUT_F + lane]));
        float v1 = __half2float(__ldg(&d_g2[s1 * OUT_F + lane]));
        float v2 = __half2float(__ldg(&d_g2[s2 * OUT_F + lane]));
        float v3 = __half2float(__ldg(&d_g2[s3 * OUT_F + lane]));
        acc += (v0 + v1) + (v2 + v3);
    }
    for (; e < end; ++e) {
        int s = __ldg(&d_srcsorted[e]);
        acc += __half2float(__ldg(&d_g2[s * OUT_F + lane]));
    }

    out[warp * OUT_F + lane] = fmaf(d_dinv[warp], acc, __ldg(&b2[lane]));
}

extern "C" void kernel_launch(void* const* d_in, const int* in_sizes, int n_in,
                              void* d_out, int out_size) {
    const float* x  = (const float*)d_in[0];
    const int*   ei = (const int*)  d_in[1];
    const float* W1 = (const float*)d_in[2];
    const float* b1 = (const float*)d_in[3];
    const float* W2 = (const float*)d_in[4];
    const float* b2 = (const float*)d_in[5];
    float* out = (float*)d_out;

    zero_cnt_kernel<<<(N_NODES / 4 + 256) / 256, 256>>>();
    count_kernel   <<<(N_EDGES / 2) / 256, 256>>>(ei);   // 3125 blocks, exact
    scan_a_kernel  <<<NB_SCAN, SCAN_BLK>>>();
    scan_b_kernel  <<<1, 128>>>();
    scan_c_kernel  <<<(N_NODES + 255) / 256, 256>>>();
    fill_kernel    <<<(N_EDGES / 2) / 256, 256>>>(ei);   // 3125 blocks, exact

    gemm1_kernel   <<<(N_NODES + 63) / 64, 256>>>(x, W1);
    gather1_kernel <<<(N_NODES * 32 + 255) / 256, 256>>>(b1);

    gemm2_kernel   <<<(N_NODES + 63) / 64, 256>>>(W2);
    gather2_kernel <<<(N_NODES * 32 + 255) / 256, 256>>>(b2, out);
}